// round 14
// baseline (speedup 1.0000x reference)
#include <cuda_runtime.h>
#include <cuda_fp16.h>

#define MBATCH 32
#define ET 4
#define NN 512
#define IN0 64
#define HID 128
#define ROWS (MBATCH*NN)      /* 16384 */
#define MAXNBR 64
#define KP0 352               /* pad(5*64+4, 32)  */
#define KP12 672              /* pad(5*128+4, 32) */
#define EPSV 1e-5f

/* transposed-weight column offsets inside g_Wt[128][WTCOLS] */
#define WT0 0
#define WT1 352
#define WT2 1024
#define WT3 1696
#define WT4 1824
#define WTCOLS 1952

#define NB_CSR    ((MBATCH*ET*NN)/8)              /* 8192 csr blocks */
#define NB_WPREP  ((HID*WTCOLS + 255)/256)        /* 976  */
#define NB_SSUM   ((MBATCH*ET*NN)/256)            /* 256  */
#define NB_STAGE0 ((MBATCH*NN*IN0/4)/256)         /* 1024 */

/* ---------------- static device scratch (no allocation) ---------------- */
__device__ float          g_inv[MBATCH*NN];
__device__ float          g_ssum[MBATCH*ET*NN];
__device__ __align__(16) unsigned short g_nbr[MBATCH*ET*NN*MAXNBR];  /* node idx */
__device__ int            g_cnt[MBATCH*ET*NN];              // clamped
__device__ int            g_cntfull[MBATCH*ET*NN];          // exact
__device__ __align__(16) __half g_A[ROWS*KP12];             // 22 MB
__device__ __align__(16) __half g_Wt[HID*WTCOLS];           // 0.5 MB
__device__ __align__(16) float  g_pre[ROWS*HID];            // 8.4 MB
__device__ __align__(16) __half g_hh[ROWS*HID];             // post-BN act, fp16
__device__ __align__(16) __half g_h16[ROWS*HID];            // inv-scaled act
__device__ __align__(16) __half g_x16[MBATCH*NN*IN0];       // inv-scaled x
__device__ float          g_bnsum[4*NN];
__device__ float          g_bnsq[4*NN];

/* ------------- 1) CSR build (+ fused weight prep in DRAM shadow) ------- */
__global__ void k_csr(const float* __restrict__ adj,
    const float* __restrict__ ws0, const float* __restrict__ we0, const float* __restrict__ be0,
    const float* __restrict__ ws1, const float* __restrict__ we1, const float* __restrict__ be1,
    const float* __restrict__ ws2, const float* __restrict__ we2, const float* __restrict__ be2,
    const float* __restrict__ w1,  const float* __restrict__ w2) {
    int blk = blockIdx.x;
    if (blk >= NB_CSR) {               /* ---- transposed weight prep ---- */
        int idx = (blk - NB_CSR) * 256 + threadIdx.x;
        if (idx >= HID * WTCOLS) return;
        int o = idx / WTCOLS, k = idx - o * WTCOLS;
        float v = 0.f;
        if (k < WT1) {
            int kk = k;
            if (kk < 64)       v = ws0[kk * HID + o];
            else if (kk < 320) { int e = (kk - 64) >> 6, j = (kk - 64) & 63;
                                 v = we0[j * (HID * ET) + o * ET + e]; }
            else if (kk < 324)   v = be0[o * ET + (kk - 320)];
        } else if (k < WT2) {
            int kk = k - WT1;
            if (kk < 128)      v = ws1[kk * HID + o];
            else if (kk < 640) { int e = (kk - 128) >> 7, j = (kk - 128) & 127;
                                 v = we1[j * (HID * ET) + o * ET + e]; }
            else if (kk < 644)   v = be1[o * ET + (kk - 640)];
        } else if (k < WT3) {
            int kk = k - WT2;
            if (kk < 128)      v = ws2[kk * HID + o];
            else if (kk < 640) { int e = (kk - 128) >> 7, j = (kk - 128) & 127;
                                 v = we2[j * (HID * ET) + o * ET + e]; }
            else if (kk < 644)   v = be2[o * ET + (kk - 640)];
        } else if (k < WT4) {
            v = w1[(k - WT3) * HID + o];
        } else {
            v = w2[(k - WT4) * HID + o];
        }
        g_Wt[o * WTCOLS + k] = __float2half_rn(v);
        return;
    }
    /* ---- CSR: one warp per (b,e,n) row ---- */
    int row  = blk * 8 + (threadIdx.x >> 5);
    int lane = threadIdx.x & 31;
    int n    = row & (NN - 1);
    const float4* p = (const float4*)(adj + (size_t)row * NN);
    unsigned short* out = g_nbr + (size_t)row * MAXNBR;
    int cnt = 0;
    for (int it = 0; it < NN / 128; it++) {
        float4 v = p[it * 32 + lane];
        int mb = (it * 32 + lane) * 4;
        float vc[4] = {v.x, v.y, v.z, v.w};
#pragma unroll
        for (int c = 0; c < 4; c++) {
            bool pr = (vc[c] != 0.f) && (mb + c != n);
            unsigned msk = __ballot_sync(0xffffffffu, pr);
            if (pr) {
                int pos = cnt + __popc(msk & ((1u << lane) - 1u));
                if (pos < MAXNBR) out[pos] = (unsigned short)(mb + c);
            }
            cnt += __popc(msk);
        }
    }
    if (lane == 0) {
        g_cnt[row]     = cnt < MAXNBR ? cnt : MAXNBR;
        g_cntfull[row] = cnt;
    }
}

/* ------------- 2) inv degree from exact counts (adj symmetric, 0/1) ---- */
__global__ void k_deg() {
    int i = blockIdx.x * 256 + threadIdx.x;
    int b = i >> 9, m = i & 511;
    int d = 0;
#pragma unroll
    for (int e = 0; e < ET; e++) d += g_cntfull[((b * ET + e) << 9) + m];
    g_inv[i] = d > 0 ? 1.f / (float)d : 0.f;
}

/* ------------- 3) fused prep: ssum | stage0 (block dispatch) ----------- */
__global__ void k_prep1(const float* __restrict__ x) {
    int blk = blockIdx.x;
    if (blk < NB_SSUM) {
        int lidx = blk * 256 + threadIdx.x;
        int b = lidx >> 11;
        int cnt = g_cnt[lidx];
        const unsigned short* nb = g_nbr + (size_t)lidx * MAXNBR;
        const float* invb = g_inv + b * NN;
        float s = 0.f;
        for (int i = 0; i < cnt; i++) s += invb[nb[i]];
        g_ssum[lidx] = s;
        if (lidx < 4 * NN) { g_bnsum[lidx] = 0.f; g_bnsq[lidx] = 0.f; }
        return;
    }
    blk -= NB_SSUM;
    {
        int i4 = blk * 256 + threadIdx.x;
        float4 v = ((const float4*)x)[i4];
        int r = i4 >> 4;
        float w = g_inv[r];
        __half2 h0 = __floats2half2_rn(w * v.x, w * v.y);
        __half2 h1 = __floats2half2_rn(w * v.z, w * v.w);
        uint2 u; u.x = *(unsigned*)&h0; u.y = *(unsigned*)&h1;
        ((uint2*)g_x16)[i4] = u;
    }
}

/* ------------- 4) sparse aggregation: 2 rows/block, dual-chain ILP ----- */
/* block = 2 consecutive A-rows (same b); warp e gathers both rows' e-list */
/* as two interleaved independent chains. Housekeeping spread over warps. */
template<int IN>
__global__ void __launch_bounds__(128, 12) k_agg2(const float* __restrict__ x0, int KP) {
    constexpr int VEC = IN / 32;   // 4 for IN=128, 2 for IN=64
    const __half* __restrict__ h16 = (IN == IN0) ? (const __half*)g_x16
                                                 : (const __half*)g_h16;
    int r0 = blockIdx.x * 2, b = r0 >> 9, n0 = r0 & 511;
    int e = threadIdx.x >> 5, lane = threadIdx.x & 31;
    __half* A0 = g_A + (size_t)r0 * KP;
    __half* A1 = A0 + KP;

    /* housekeeping: warp0/1 self-copy, warp2/3 s-values + pad */
    if (e == 0) {
        if (IN == IN0) {
            float2 v = *(const float2*)(x0 + (size_t)r0 * IN + lane * 2);
            *(__half2*)(A0 + lane * 2) = __floats2half2_rn(v.x, v.y);
        } else {
            *(uint2*)(A0 + lane * 4) =
                *(const uint2*)((const __half*)g_hh + (size_t)r0 * IN + lane * 4);
        }
    } else if (e == 1) {
        if (IN == IN0) {
            float2 v = *(const float2*)(x0 + (size_t)(r0 + 1) * IN + lane * 2);
            *(__half2*)(A1 + lane * 2) = __floats2half2_rn(v.x, v.y);
        } else {
            *(uint2*)(A1 + lane * 4) =
                *(const uint2*)((const __half*)g_hh + (size_t)(r0 + 1) * IN + lane * 4);
        }
    } else if (e == 2) {
        if (lane < ET)
            A0[5 * IN + lane] = __float2half_rn(g_ssum[((b * ET + lane) << 9) + n0]);
        else if (lane >= 4 && lane < 32 && lane - 4 < KP - 5 * IN - 4)
            A0[5 * IN + lane] = __half(0.f);
    } else {
        if (lane < ET)
            A1[5 * IN + lane] = __float2half_rn(g_ssum[((b * ET + lane) << 9) + n0 + 1]);
        else if (lane >= 4 && lane < 32 && lane - 4 < KP - 5 * IN - 4)
            A1[5 * IN + lane] = __half(0.f);
    }

    int lidx0 = ((b * ET + e) << 9) + n0;
    int c0 = g_cnt[lidx0], c1 = g_cnt[lidx0 + 1];
    const uint2* nbq0 = (const uint2*)(g_nbr + (size_t)lidx0 * MAXNBR);
    const uint2* nbq1 = (const uint2*)(g_nbr + (size_t)(lidx0 + 1) * MAXNBR);
    const __half* hb = h16 + (size_t)b * NN * IN + lane * VEC;

    float a0[VEC], a1[VEC];
#pragma unroll
    for (int c = 0; c < VEC; c++) { a0[c] = 0.f; a1[c] = 0.f; }

    uint2 q0 = nbq0[0], q1 = nbq1[0];
    int i0 = 0, i1 = 0;
    for (;;) {
        bool d0 = (i0 + 4 <= c0), d1 = (i1 + 4 <= c1);
        if (!d0 && !d1) break;
        if (d0) {
            int g = (i0 >> 2) + 1;
            uint2 qn = nbq0[g < 16 ? g : 15];
            int m0 = q0.x & 0xffff, m1 = q0.x >> 16;
            int m2 = q0.y & 0xffff, m3 = q0.y >> 16;
            if (VEC == 4) {
                uint2 f0 = *(const uint2*)(hb + (size_t)m0 * IN);
                uint2 f1 = *(const uint2*)(hb + (size_t)m1 * IN);
                uint2 f2 = *(const uint2*)(hb + (size_t)m2 * IN);
                uint2 f3 = *(const uint2*)(hb + (size_t)m3 * IN);
                __half2 sx = __hadd2(__hadd2(*(__half2*)&f0.x, *(__half2*)&f1.x),
                                     __hadd2(*(__half2*)&f2.x, *(__half2*)&f3.x));
                __half2 sy = __hadd2(__hadd2(*(__half2*)&f0.y, *(__half2*)&f1.y),
                                     __hadd2(*(__half2*)&f2.y, *(__half2*)&f3.y));
                float2 fa = __half22float2(sx), fb = __half22float2(sy);
                a0[0] += fa.x; a0[1] += fa.y; a0[2] += fb.x; a0[3] += fb.y;
            } else {
                unsigned f0 = *(const unsigned*)(hb + (size_t)m0 * IN);
                unsigned f1 = *(const unsigned*)(hb + (size_t)m1 * IN);
                unsigned f2 = *(const unsigned*)(hb + (size_t)m2 * IN);
                unsigned f3 = *(const unsigned*)(hb + (size_t)m3 * IN);
                __half2 s = __hadd2(__hadd2(*(__half2*)&f0, *(__half2*)&f1),
                                    __hadd2(*(__half2*)&f2, *(__half2*)&f3));
                float2 fa = __half22float2(s);
                a0[0] += fa.x; a0[1] += fa.y;
            }
            q0 = qn; i0 += 4;
        }
        if (d1) {
            int g = (i1 >> 2) + 1;
            uint2 qn = nbq1[g < 16 ? g : 15];
            int m0 = q1.x & 0xffff, m1 = q1.x >> 16;
            int m2 = q1.y & 0xffff, m3 = q1.y >> 16;
            if (VEC == 4) {
                uint2 f0 = *(const uint2*)(hb + (size_t)m0 * IN);
                uint2 f1 = *(const uint2*)(hb + (size_t)m1 * IN);
                uint2 f2 = *(const uint2*)(hb + (size_t)m2 * IN);
                uint2 f3 = *(const uint2*)(hb + (size_t)m3 * IN);
                __half2 sx = __hadd2(__hadd2(*(__half2*)&f0.x, *(__half2*)&f1.x),
                                     __hadd2(*(__half2*)&f2.x, *(__half2*)&f3.x));
                __half2 sy = __hadd2(__hadd2(*(__half2*)&f0.y, *(__half2*)&f1.y),
                                     __hadd2(*(__half2*)&f2.y, *(__half2*)&f3.y));
                float2 fa = __half22float2(sx), fb = __half22float2(sy);
                a1[0] += fa.x; a1[1] += fa.y; a1[2] += fb.x; a1[3] += fb.y;
            } else {
                unsigned f0 = *(const unsigned*)(hb + (size_t)m0 * IN);
                unsigned f1 = *(const unsigned*)(hb + (size_t)m1 * IN);
                unsigned f2 = *(const unsigned*)(hb + (size_t)m2 * IN);
                unsigned f3 = *(const unsigned*)(hb + (size_t)m3 * IN);
                __half2 s = __hadd2(__hadd2(*(__half2*)&f0, *(__half2*)&f1),
                                    __hadd2(*(__half2*)&f2, *(__half2*)&f3));
                float2 fa = __half22float2(s);
                a1[0] += fa.x; a1[1] += fa.y;
            }
            q1 = qn; i1 += 4;
        }
    }
    const unsigned short* nb0 = (const unsigned short*)nbq0;
    const unsigned short* nb1 = (const unsigned short*)nbq1;
    for (; i0 < c0; i0++) {
        int m = nb0[i0];
        if (VEC == 4) {
            uint2 f0 = *(const uint2*)(hb + (size_t)m * IN);
            float2 fa = __half22float2(*(__half2*)&f0.x);
            float2 fb = __half22float2(*(__half2*)&f0.y);
            a0[0] += fa.x; a0[1] += fa.y; a0[2] += fb.x; a0[3] += fb.y;
        } else {
            unsigned f0 = *(const unsigned*)(hb + (size_t)m * IN);
            float2 fa = __half22float2(*(__half2*)&f0);
            a0[0] += fa.x; a0[1] += fa.y;
        }
    }
    for (; i1 < c1; i1++) {
        int m = nb1[i1];
        if (VEC == 4) {
            uint2 f0 = *(const uint2*)(hb + (size_t)m * IN);
            float2 fa = __half22float2(*(__half2*)&f0.x);
            float2 fb = __half22float2(*(__half2*)&f0.y);
            a1[0] += fa.x; a1[1] += fa.y; a1[2] += fb.x; a1[3] += fb.y;
        } else {
            unsigned f0 = *(const unsigned*)(hb + (size_t)m * IN);
            float2 fa = __half22float2(*(__half2*)&f0);
            a1[0] += fa.x; a1[1] += fa.y;
        }
    }

    if (VEC == 4) {
        __half2 o0 = __floats2half2_rn(a0[0], a0[1]);
        __half2 o1 = __floats2half2_rn(a0[2], a0[3]);
        uint2 u; u.x = *(unsigned*)&o0; u.y = *(unsigned*)&o1;
        *(uint2*)(A0 + IN + e * IN + lane * 4) = u;
        __half2 p0 = __floats2half2_rn(a1[0], a1[1]);
        __half2 p1 = __floats2half2_rn(a1[2], a1[3]);
        uint2 w; w.x = *(unsigned*)&p0; w.y = *(unsigned*)&p1;
        *(uint2*)(A1 + IN + e * IN + lane * 4) = w;
    } else {
        *(__half2*)(A0 + IN + e * IN + lane * 2) = __floats2half2_rn(a0[0], a0[1]);
        *(__half2*)(A1 + IN + e * IN + lane * 2) = __floats2half2_rn(a1[0], a1[1]);
    }
}

/* ------------- 5) FP16 tensor GEMM (m16n8k16, ldmatrix) + BN stats ----- */
#define SROW 40   /* smem row pitch in halfs (32 data + 8 pad) */

__device__ __forceinline__ unsigned smaddr(const void* p) {
    return (unsigned)__cvta_generic_to_shared(p);
}
__device__ __forceinline__ void cpasync16(unsigned s, const void* g) {
    asm volatile("cp.async.cg.shared.global [%0], [%1], 16;\n" :: "r"(s), "l"(g));
}
__device__ __forceinline__ void ldsm4(unsigned& r0, unsigned& r1, unsigned& r2,
                                      unsigned& r3, unsigned addr) {
    asm volatile("ldmatrix.sync.aligned.m8n8.x4.shared.b16 {%0,%1,%2,%3}, [%4];\n"
                 : "=r"(r0), "=r"(r1), "=r"(r2), "=r"(r3) : "r"(addr));
}

__global__ void __launch_bounds__(256) k_gemm(int KP, const float* __restrict__ bias,
                                              int srcH, float* __restrict__ Cout,
                                              int wofs, int sb) {
    const __half* A = srcH ? (const __half*)g_hh : (const __half*)g_A;
    float* C = Cout ? Cout : (float*)g_pre;

    __shared__ __half sA[2][128 * SROW];
    __shared__ __half sB[2][128 * SROW];
    const unsigned BUFB = 128 * SROW * 2;        /* bytes per buffer */

    int tid = threadIdx.x;
    int lane = tid & 31, warp = tid >> 5;
    int wm = (warp >> 1) * 32, wn = (warp & 1) * 64;
    int grp = lane >> 2, qid = lane & 3;
    int rowbase = blockIdx.x * 128;
    int KB = KP >> 5;

    unsigned aBase = smaddr(&sA[0][0]);
    unsigned bBase = smaddr(&sB[0][0]);
    int l7 = lane & 7, lb3 = (lane >> 3) & 1, lb4 = lane >> 4;
    unsigned aOff[2], bOff[4];
#pragma unroll
    for (int mi = 0; mi < 2; mi++)
        aOff[mi] = ((wm + mi * 16 + lb3 * 8 + l7) * SROW + lb4 * 8) * 2;
#pragma unroll
    for (int p = 0; p < 4; p++)
        bOff[p] = ((wn + p * 16 + lb4 * 8 + l7) * SROW + lb3 * 8) * 2;

    float acc[2][8][4];
#pragma unroll
    for (int a = 0; a < 2; a++)
#pragma unroll
        for (int bq = 0; bq < 8; bq++)
#pragma unroll
            for (int c = 0; c < 4; c++) acc[a][bq][c] = 0.f;

    auto issue = [&](int kb, int buf) {
        int kof = kb * 32;
#pragma unroll
        for (int i = 0; i < 2; i++) {
            int c = tid + i * 256, row = c >> 2, q = c & 3;
            cpasync16(smaddr(&sA[buf][row * SROW + q * 8]),
                      A + (size_t)(rowbase + row) * KP + kof + q * 8);
            cpasync16(smaddr(&sB[buf][row * SROW + q * 8]),
                      (const __half*)g_Wt + (size_t)row * WTCOLS + wofs + kof + q * 8);
        }
        asm volatile("cp.async.commit_group;\n" ::);
    };

    issue(0, 0);
    for (int kb = 0; kb < KB; kb++) {
        int buf = kb & 1;
        if (kb + 1 < KB) {
            issue(kb + 1, buf ^ 1);
            asm volatile("cp.async.wait_group 1;\n" ::);
        } else {
            asm volatile("cp.async.wait_group 0;\n" ::);
        }
        __syncthreads();

#pragma unroll
        for (int ks = 0; ks < 2; ks++) {
            unsigned kby = ks * 32 + buf * BUFB;
            unsigned bf[8][2];
#pragma unroll
            for (int p = 0; p < 4; p++)
                ldsm4(bf[2*p][0], bf[2*p][1], bf[2*p+1][0], bf[2*p+1][1],
                      bBase + bOff[p] + kby);
#pragma unroll
            for (int mi = 0; mi < 2; mi++) {
                unsigned a0, a1, a2, a3;
                ldsm4(a0, a1, a2, a3, aBase + aOff[mi] + kby);
#pragma unroll
                for (int ni = 0; ni < 8; ni++) {
                    asm volatile(
                        "mma.sync.aligned.m16n8k16.row.col.f32.f16.f16.f32 "
                        "{%0,%1,%2,%3}, {%4,%5,%6,%7}, {%8,%9}, {%0,%1,%2,%3};\n"
                        : "+f"(acc[mi][ni][0]), "+f"(acc[mi][ni][1]),
                          "+f"(acc[mi][ni][2]), "+f"(acc[mi][ni][3])
                        : "r"(a0), "r"(a1), "r"(a2), "r"(a3),
                          "r"(bf[ni][0]), "r"(bf[ni][1]));
                }
            }
        }
        __syncthreads();
    }

    /* epilogue: +bias, store, per-row BN partial sums */
    float rs[2][2] = {{0.f,0.f},{0.f,0.f}};
    float rq[2][2] = {{0.f,0.f},{0.f,0.f}};
#pragma unroll
    for (int mi = 0; mi < 2; mi++) {
        int row = rowbase + wm + mi * 16 + grp;
#pragma unroll
        for (int ni = 0; ni < 8; ni++) {
            int col = wn + ni * 8 + qid * 2;
            float b0 = bias[col], b1 = bias[col + 1];
            float v0 = acc[mi][ni][0] + b0, v1 = acc[mi][ni][1] + b1;
            float v2 = acc[mi][ni][2] + b0, v3 = acc[mi][ni][3] + b1;
            C[(size_t)row * HID + col]           = v0;
            C[(size_t)row * HID + col + 1]       = v1;
            C[(size_t)(row + 8) * HID + col]     = v2;
            C[(size_t)(row + 8) * HID + col + 1] = v3;
            rs[mi][0] += v0 + v1; rq[mi][0] += v0 * v0 + v1 * v1;
            rs[mi][1] += v2 + v3; rq[mi][1] += v2 * v2 + v3 * v3;
        }
    }
    if (sb >= 0) {
#pragma unroll
        for (int mi = 0; mi < 2; mi++)
#pragma unroll
            for (int rr = 0; rr < 2; rr++) {
                rs[mi][rr] += __shfl_xor_sync(0xffffffffu, rs[mi][rr], 1);
                rs[mi][rr] += __shfl_xor_sync(0xffffffffu, rs[mi][rr], 2);
                rq[mi][rr] += __shfl_xor_sync(0xffffffffu, rq[mi][rr], 1);
                rq[mi][rr] += __shfl_xor_sync(0xffffffffu, rq[mi][rr], 2);
            }
        if (qid == 0) {
#pragma unroll
            for (int mi = 0; mi < 2; mi++)
#pragma unroll
                for (int rr = 0; rr < 2; rr++) {
                    int row = rowbase + wm + mi * 16 + grp + rr * 8;
                    int n = row & 511;
                    atomicAdd(&g_bnsum[sb * NN + n], rs[mi][rr]);
                    atomicAdd(&g_bnsq [sb * NN + n], rq[mi][rr]);
                }
        }
    }
}

/* ------------- 6) BN finalize + apply + ReLU (fp16 stages) ------------- */
template<bool H16>
__global__ void k_bnapply(const float* __restrict__ g, const float* __restrict__ bb,
                          int sb) {
    int i4 = blockIdx.x * 256 + threadIdx.x;
    float4 v = ((const float4*)g_pre)[i4];
    int r = i4 >> 5;
    int n = r & 511;
    const float invC = 1.f / (float)(MBATCH * HID);
    float mean = g_bnsum[sb * NN + n] * invC;
    float var  = g_bnsq [sb * NN + n] * invC - mean * mean;
    var = fmaxf(var, 0.f);
    float sc = g[n] * rsqrtf(var + EPSV);
    float sh = bb[n] - mean * sc;
    float x0 = fmaxf(v.x * sc + sh, 0.f);
    float x1 = fmaxf(v.y * sc + sh, 0.f);
    float x2 = fmaxf(v.z * sc + sh, 0.f);
    float x3 = fmaxf(v.w * sc + sh, 0.f);
    __half2 p0 = __floats2half2_rn(x0, x1);
    __half2 p1 = __floats2half2_rn(x2, x3);
    uint2 u; u.x = *(unsigned*)&p0; u.y = *(unsigned*)&p1;
    ((uint2*)g_hh)[i4] = u;
    if (H16) {
        float w = g_inv[r];
        __half2 h0 = __floats2half2_rn(w * x0, w * x1);
        __half2 h1 = __floats2half2_rn(w * x2, w * x3);
        uint2 u2; u2.x = *(unsigned*)&h0; u2.y = *(unsigned*)&h1;
        ((uint2*)g_h16)[i4] = u2;
    }
}

/* ---------------- driver ------------------------------------------------ */
extern "C" void kernel_launch(void* const* d_in, const int* in_sizes, int n_in,
                              void* d_out, int out_size) {
    const float* x   = (const float*)d_in[0];
    const float* adj = (const float*)d_in[1];
    const float* ws[3] = {(const float*)d_in[2],  (const float*)d_in[8],  (const float*)d_in[14]};
    const float* bs[3] = {(const float*)d_in[3],  (const float*)d_in[9],  (const float*)d_in[15]};
    const float* we[3] = {(const float*)d_in[4],  (const float*)d_in[10], (const float*)d_in[16]};
    const float* be[3] = {(const float*)d_in[5],  (const float*)d_in[11], (const float*)d_in[17]};
    const float* bg[3] = {(const float*)d_in[6],  (const float*)d_in[12], (const float*)d_in[18]};
    const float* bb[3] = {(const float*)d_in[7],  (const float*)d_in[13], (const float*)d_in[19]};
    const float* w1  = (const float*)d_in[20];
    const float* b1  = (const float*)d_in[21];
    const float* bfg = (const float*)d_in[22];
    const float* bfb = (const float*)d_in[23];
    const float* w2  = (const float*)d_in[24];
    const float* b2  = (const float*)d_in[25];

    (void)in_sizes; (void)n_in; (void)out_size;

    k_csr<<<NB_CSR + NB_WPREP, 256>>>(adj,
        ws[0], we[0], be[0], ws[1], we[1], be[1], ws[2], we[2], be[2], w1, w2);
    k_deg<<<(MBATCH * NN) / 256, 256>>>();
    k_prep1<<<NB_SSUM + NB_STAGE0, 256>>>(x);

    /* layer 0 */
    k_agg2<IN0><<<ROWS / 2, 128>>>(x, KP0);
    k_gemm<<<ROWS / 128, 256>>>(KP0, bs[0], 0, nullptr, WT0, 0);
    k_bnapply<true><<<ROWS * HID / 4 / 256, 256>>>(bg[0], bb[0], 0);

    /* layer 1 */
    k_agg2<HID><<<ROWS / 2, 128>>>((const float*)nullptr, KP12);
    k_gemm<<<ROWS / 128, 256>>>(KP12, bs[1], 0, nullptr, WT1, 1);
    k_bnapply<true><<<ROWS * HID / 4 / 256, 256>>>(bg[1], bb[1], 1);

    /* layer 2 */
    k_agg2<HID><<<ROWS / 2, 128>>>((const float*)nullptr, KP12);
    k_gemm<<<ROWS / 128, 256>>>(KP12, bs[2], 0, nullptr, WT2, 2);
    k_bnapply<true><<<ROWS * HID / 4 / 256, 256>>>(bg[2], bb[2], 2);

    /* final MLP */
    k_gemm<<<ROWS / 128, 256>>>(HID, b1, 1, nullptr, WT3, 3);
    k_bnapply<false><<<ROWS * HID / 4 / 256, 256>>>(bfg, bfb, 3);
    k_gemm<<<ROWS / 128, 256>>>(HID, b2, 1, (float*)d_out, WT4, -1);
}

// round 15
// speedup vs baseline: 1.6704x; 1.6704x over previous
#include <cuda_runtime.h>
#include <cuda_fp16.h>

#define MBATCH 32
#define ET 4
#define NN 512
#define IN0 64
#define HID 128
#define ROWS (MBATCH*NN)      /* 16384 */
#define MAXNBR 64
#define KP0 352               /* pad(5*64+4, 32)  */
#define KP12 672              /* pad(5*128+4, 32) */
#define EPSV 1e-5f

/* transposed-weight column offsets inside g_Wt[128][WTCOLS] */
#define WT0 0
#define WT1 352
#define WT2 1024
#define WT3 1696
#define WT4 1824
#define WTCOLS 1952

#define NB_CSR    ((MBATCH*ET*NN)/8)              /* 8192 csr blocks */
#define NB_WPREP  ((HID*WTCOLS + 255)/256)        /* 976  */
#define NB_SSUM   ((MBATCH*ET*NN)/256)            /* 256  */
#define NB_STAGE0 ((MBATCH*NN*IN0/4)/256)         /* 1024 */

/* ---------------- static device scratch (no allocation) ---------------- */
__device__ float          g_inv[MBATCH*NN];
__device__ float          g_ssum[MBATCH*ET*NN];
__device__ __align__(16) unsigned short g_nbr[MBATCH*ET*NN*MAXNBR];  /* node idx */
__device__ int            g_cnt[MBATCH*ET*NN];              // clamped
__device__ int            g_cntfull[MBATCH*ET*NN];          // exact
__device__ __align__(16) __half g_A[ROWS*KP12];             // 22 MB
__device__ __align__(16) __half g_Wt[HID*WTCOLS];           // 0.5 MB
__device__ __align__(16) float  g_pre[ROWS*HID];            // 8.4 MB
__device__ __align__(16) __half g_hh[ROWS*HID];             // post-BN act, fp16
__device__ __align__(16) __half g_h16[ROWS*HID];            // inv-scaled act
__device__ __align__(16) __half g_x16[MBATCH*NN*IN0];       // inv-scaled x
__device__ float          g_bnsum[4*NN];
__device__ float          g_bnsq[4*NN];

/* ------------- 1) CSR build (+ fused weight prep in DRAM shadow) ------- */
__global__ void k_csr(const float* __restrict__ adj,
    const float* __restrict__ ws0, const float* __restrict__ we0, const float* __restrict__ be0,
    const float* __restrict__ ws1, const float* __restrict__ we1, const float* __restrict__ be1,
    const float* __restrict__ ws2, const float* __restrict__ we2, const float* __restrict__ be2,
    const float* __restrict__ w1,  const float* __restrict__ w2) {
    int blk = blockIdx.x;
    if (blk >= NB_CSR) {               /* ---- transposed weight prep ---- */
        int idx = (blk - NB_CSR) * 256 + threadIdx.x;
        if (idx >= HID * WTCOLS) return;
        int o = idx / WTCOLS, k = idx - o * WTCOLS;
        float v = 0.f;
        if (k < WT1) {
            int kk = k;
            if (kk < 64)       v = ws0[kk * HID + o];
            else if (kk < 320) { int e = (kk - 64) >> 6, j = (kk - 64) & 63;
                                 v = we0[j * (HID * ET) + o * ET + e]; }
            else if (kk < 324)   v = be0[o * ET + (kk - 320)];
        } else if (k < WT2) {
            int kk = k - WT1;
            if (kk < 128)      v = ws1[kk * HID + o];
            else if (kk < 640) { int e = (kk - 128) >> 7, j = (kk - 128) & 127;
                                 v = we1[j * (HID * ET) + o * ET + e]; }
            else if (kk < 644)   v = be1[o * ET + (kk - 640)];
        } else if (k < WT3) {
            int kk = k - WT2;
            if (kk < 128)      v = ws2[kk * HID + o];
            else if (kk < 640) { int e = (kk - 128) >> 7, j = (kk - 128) & 127;
                                 v = we2[j * (HID * ET) + o * ET + e]; }
            else if (kk < 644)   v = be2[o * ET + (kk - 640)];
        } else if (k < WT4) {
            v = w1[(k - WT3) * HID + o];
        } else {
            v = w2[(k - WT4) * HID + o];
        }
        g_Wt[o * WTCOLS + k] = __float2half_rn(v);
        return;
    }
    /* ---- CSR: one warp per (b,e,n) row ---- */
    int row  = blk * 8 + (threadIdx.x >> 5);
    int lane = threadIdx.x & 31;
    int n    = row & (NN - 1);
    const float4* p = (const float4*)(adj + (size_t)row * NN);
    unsigned short* out = g_nbr + (size_t)row * MAXNBR;
    int cnt = 0;
    for (int it = 0; it < NN / 128; it++) {
        float4 v = p[it * 32 + lane];
        int mb = (it * 32 + lane) * 4;
        float vc[4] = {v.x, v.y, v.z, v.w};
#pragma unroll
        for (int c = 0; c < 4; c++) {
            bool pr = (vc[c] != 0.f) && (mb + c != n);
            unsigned msk = __ballot_sync(0xffffffffu, pr);
            if (pr) {
                int pos = cnt + __popc(msk & ((1u << lane) - 1u));
                if (pos < MAXNBR) out[pos] = (unsigned short)(mb + c);
            }
            cnt += __popc(msk);
        }
    }
    if (lane == 0) {
        g_cnt[row]     = cnt < MAXNBR ? cnt : MAXNBR;
        g_cntfull[row] = cnt;
    }
}

/* ------------- 2) inv degree from exact counts (adj symmetric, 0/1) ---- */
__global__ void k_deg() {
    int i = blockIdx.x * 256 + threadIdx.x;
    int b = i >> 9, m = i & 511;
    int d = 0;
#pragma unroll
    for (int e = 0; e < ET; e++) d += g_cntfull[((b * ET + e) << 9) + m];
    g_inv[i] = d > 0 ? 1.f / (float)d : 0.f;
}

/* ------------- 3) fused prep: ssum | stage0 (block dispatch) ----------- */
__global__ void k_prep1(const float* __restrict__ x) {
    int blk = blockIdx.x;
    if (blk < NB_SSUM) {
        int lidx = blk * 256 + threadIdx.x;
        int b = lidx >> 11;
        int cnt = g_cnt[lidx];
        const unsigned short* nb = g_nbr + (size_t)lidx * MAXNBR;
        const float* invb = g_inv + b * NN;
        float s = 0.f;
        for (int i = 0; i < cnt; i++) s += invb[nb[i]];
        g_ssum[lidx] = s;
        if (lidx < 4 * NN) { g_bnsum[lidx] = 0.f; g_bnsq[lidx] = 0.f; }
        return;
    }
    blk -= NB_SSUM;
    {
        int i4 = blk * 256 + threadIdx.x;
        float4 v = ((const float4*)x)[i4];
        int r = i4 >> 4;
        float w = g_inv[r];
        __half2 h0 = __floats2half2_rn(w * v.x, w * v.y);
        __half2 h1 = __floats2half2_rn(w * v.z, w * v.w);
        uint2 u; u.x = *(unsigned*)&h0; u.y = *(unsigned*)&h1;
        ((uint2*)g_x16)[i4] = u;
    }
}

/* ------------- 4) sparse aggregation: u16 idx + fp16 tree-sum ---------- */
/* R13 form, frozen: single chain/warp, 32-reg cap, 100% theor. occupancy */
template<int IN>
__global__ void __launch_bounds__(128, 16) k_agg(const float* __restrict__ x0, int KP) {
    constexpr int VEC = IN / 32;   // 4 for IN=128, 2 for IN=64
    const __half* __restrict__ h16 = (IN == IN0) ? (const __half*)g_x16
                                                 : (const __half*)g_h16;
    int r = blockIdx.x, b = r >> 9, n = r & 511;
    int warp = threadIdx.x >> 5, lane = threadIdx.x & 31;
    __half* Arow = g_A + (size_t)r * KP;

    if (warp == 0) {   /* self-feature copy */
        if (IN == IN0) {
            float2 v = *(const float2*)(x0 + (size_t)r * IN + lane * 2);
            *(__half2*)(Arow + lane * 2) = __floats2half2_rn(v.x, v.y);
        } else {
            *(uint2*)(Arow + lane * 4) =
                *(const uint2*)((const __half*)g_hh + (size_t)r * IN + lane * 4);
        }
    }
    if (warp == 1) {   /* s-values + zero-pad tail */
        if (lane < ET)
            Arow[5 * IN + lane] = __float2half_rn(g_ssum[((b * ET + lane) << 9) + n]);
        for (int k = 5 * IN + 4 + lane; k < KP; k += 32) Arow[k] = __half(0.f);
    }

    int e = warp;
    int lidx = ((b * ET + e) << 9) + n;
    int cnt = g_cnt[lidx];
    const unsigned short* nb = g_nbr + (size_t)lidx * MAXNBR;
    const uint2* nbq = (const uint2*)nb;      /* 16 groups of 4 u16 */
    const __half* hb = h16 + (size_t)b * NN * IN + lane * VEC;

    float acc[VEC];
#pragma unroll
    for (int c = 0; c < VEC; c++) acc[c] = 0.f;

    int i = 0;
    if (cnt >= 4) {
        uint2 qc = nbq[0];                    /* index prefetch, distance 1 */
        for (; i + 4 <= cnt; i += 4) {
            int g = (i >> 2) + 1;
            uint2 qn = nbq[g < 16 ? g : 15];  /* clamp: no OOB on last row */
            int m0 = qc.x & 0xffff, m1 = qc.x >> 16;
            int m2 = qc.y & 0xffff, m3 = qc.y >> 16;
            if (VEC == 4) {
                uint2 f0 = *(const uint2*)(hb + (size_t)m0 * IN);
                uint2 f1 = *(const uint2*)(hb + (size_t)m1 * IN);
                uint2 f2 = *(const uint2*)(hb + (size_t)m2 * IN);
                uint2 f3 = *(const uint2*)(hb + (size_t)m3 * IN);
                /* fp16 depth-2 tree per half2 column, one convert per batch */
                __half2 sx = __hadd2(__hadd2(*(__half2*)&f0.x, *(__half2*)&f1.x),
                                     __hadd2(*(__half2*)&f2.x, *(__half2*)&f3.x));
                __half2 sy = __hadd2(__hadd2(*(__half2*)&f0.y, *(__half2*)&f1.y),
                                     __hadd2(*(__half2*)&f2.y, *(__half2*)&f3.y));
                float2 a = __half22float2(sx);
                float2 bb2 = __half22float2(sy);
                acc[0] += a.x; acc[1] += a.y; acc[2] += bb2.x; acc[3] += bb2.y;
            } else {
                unsigned f0 = *(const unsigned*)(hb + (size_t)m0 * IN);
                unsigned f1 = *(const unsigned*)(hb + (size_t)m1 * IN);
                unsigned f2 = *(const unsigned*)(hb + (size_t)m2 * IN);
                unsigned f3 = *(const unsigned*)(hb + (size_t)m3 * IN);
                __half2 s = __hadd2(__hadd2(*(__half2*)&f0, *(__half2*)&f1),
                                    __hadd2(*(__half2*)&f2, *(__half2*)&f3));
                float2 a = __half22float2(s);
                acc[0] += a.x; acc[1] += a.y;
            }
            qc = qn;
        }
    }
    for (; i < cnt; i++) {
        int m = nb[i];
        if (VEC == 4) {
            uint2 f0 = *(const uint2*)(hb + (size_t)m * IN);
            float2 a = __half22float2(*(__half2*)&f0.x);
            float2 bb2 = __half22float2(*(__half2*)&f0.y);
            acc[0] += a.x; acc[1] += a.y; acc[2] += bb2.x; acc[3] += bb2.y;
        } else {
            unsigned f0 = *(const unsigned*)(hb + (size_t)m * IN);
            float2 a = __half22float2(*(__half2*)&f0);
            acc[0] += a.x; acc[1] += a.y;
        }
    }

    if (VEC == 4) {
        __half2 o0 = __floats2half2_rn(acc[0], acc[1]);
        __half2 o1 = __floats2half2_rn(acc[2], acc[3]);
        uint2 u; u.x = *(unsigned*)&o0; u.y = *(unsigned*)&o1;
        *(uint2*)(Arow + IN + e * IN + lane * 4) = u;
    } else {
        *(__half2*)(Arow + IN + e * IN + lane * 2) = __floats2half2_rn(acc[0], acc[1]);
    }
}

/* ------------- 5) FP16 tensor GEMM (m16n8k16, ldmatrix) + BN stats ----- */
#define SROW 40   /* smem row pitch in halfs (32 data + 8 pad) */

__device__ __forceinline__ unsigned smaddr(const void* p) {
    return (unsigned)__cvta_generic_to_shared(p);
}
__device__ __forceinline__ void cpasync16(unsigned s, const void* g) {
    asm volatile("cp.async.cg.shared.global [%0], [%1], 16;\n" :: "r"(s), "l"(g));
}
__device__ __forceinline__ void ldsm4(unsigned& r0, unsigned& r1, unsigned& r2,
                                      unsigned& r3, unsigned addr) {
    asm volatile("ldmatrix.sync.aligned.m8n8.x4.shared.b16 {%0,%1,%2,%3}, [%4];\n"
                 : "=r"(r0), "=r"(r1), "=r"(r2), "=r"(r3) : "r"(addr));
}

__global__ void __launch_bounds__(256) k_gemm(int KP, const float* __restrict__ bias,
                                              int srcH, float* __restrict__ Cout,
                                              int wofs, int sb) {
    const __half* A = srcH ? (const __half*)g_hh : (const __half*)g_A;
    float* C = Cout ? Cout : (float*)g_pre;

    __shared__ __half sA[2][128 * SROW];
    __shared__ __half sB[2][128 * SROW];
    const unsigned BUFB = 128 * SROW * 2;        /* bytes per buffer */

    int tid = threadIdx.x;
    int lane = tid & 31, warp = tid >> 5;
    int wm = (warp >> 1) * 32, wn = (warp & 1) * 64;
    int grp = lane >> 2, qid = lane & 3;
    int rowbase = blockIdx.x * 128;
    int KB = KP >> 5;

    unsigned aBase = smaddr(&sA[0][0]);
    unsigned bBase = smaddr(&sB[0][0]);
    int l7 = lane & 7, lb3 = (lane >> 3) & 1, lb4 = lane >> 4;
    unsigned aOff[2], bOff[4];
#pragma unroll
    for (int mi = 0; mi < 2; mi++)
        aOff[mi] = ((wm + mi * 16 + lb3 * 8 + l7) * SROW + lb4 * 8) * 2;
#pragma unroll
    for (int p = 0; p < 4; p++)
        bOff[p] = ((wn + p * 16 + lb4 * 8 + l7) * SROW + lb3 * 8) * 2;

    float acc[2][8][4];
#pragma unroll
    for (int a = 0; a < 2; a++)
#pragma unroll
        for (int bq = 0; bq < 8; bq++)
#pragma unroll
            for (int c = 0; c < 4; c++) acc[a][bq][c] = 0.f;

    auto issue = [&](int kb, int buf) {
        int kof = kb * 32;
#pragma unroll
        for (int i = 0; i < 2; i++) {
            int c = tid + i * 256, row = c >> 2, q = c & 3;
            cpasync16(smaddr(&sA[buf][row * SROW + q * 8]),
                      A + (size_t)(rowbase + row) * KP + kof + q * 8);
            cpasync16(smaddr(&sB[buf][row * SROW + q * 8]),
                      (const __half*)g_Wt + (size_t)row * WTCOLS + wofs + kof + q * 8);
        }
        asm volatile("cp.async.commit_group;\n" ::);
    };

    issue(0, 0);
    for (int kb = 0; kb < KB; kb++) {
        int buf = kb & 1;
        if (kb + 1 < KB) {
            issue(kb + 1, buf ^ 1);
            asm volatile("cp.async.wait_group 1;\n" ::);
        } else {
            asm volatile("cp.async.wait_group 0;\n" ::);
        }
        __syncthreads();

#pragma unroll
        for (int ks = 0; ks < 2; ks++) {
            unsigned kby = ks * 32 + buf * BUFB;
            unsigned bf[8][2];
#pragma unroll
            for (int p = 0; p < 4; p++)
                ldsm4(bf[2*p][0], bf[2*p][1], bf[2*p+1][0], bf[2*p+1][1],
                      bBase + bOff[p] + kby);
#pragma unroll
            for (int mi = 0; mi < 2; mi++) {
                unsigned a0, a1, a2, a3;
                ldsm4(a0, a1, a2, a3, aBase + aOff[mi] + kby);
#pragma unroll
                for (int ni = 0; ni < 8; ni++) {
                    asm volatile(
                        "mma.sync.aligned.m16n8k16.row.col.f32.f16.f16.f32 "
                        "{%0,%1,%2,%3}, {%4,%5,%6,%7}, {%8,%9}, {%0,%1,%2,%3};\n"
                        : "+f"(acc[mi][ni][0]), "+f"(acc[mi][ni][1]),
                          "+f"(acc[mi][ni][2]), "+f"(acc[mi][ni][3])
                        : "r"(a0), "r"(a1), "r"(a2), "r"(a3),
                          "r"(bf[ni][0]), "r"(bf[ni][1]));
                }
            }
        }
        __syncthreads();
    }

    /* epilogue: +bias, store, per-row BN partial sums */
    float rs[2][2] = {{0.f,0.f},{0.f,0.f}};
    float rq[2][2] = {{0.f,0.f},{0.f,0.f}};
#pragma unroll
    for (int mi = 0; mi < 2; mi++) {
        int row = rowbase + wm + mi * 16 + grp;
#pragma unroll
        for (int ni = 0; ni < 8; ni++) {
            int col = wn + ni * 8 + qid * 2;
            float b0 = bias[col], b1 = bias[col + 1];
            float v0 = acc[mi][ni][0] + b0, v1 = acc[mi][ni][1] + b1;
            float v2 = acc[mi][ni][2] + b0, v3 = acc[mi][ni][3] + b1;
            C[(size_t)row * HID + col]           = v0;
            C[(size_t)row * HID + col + 1]       = v1;
            C[(size_t)(row + 8) * HID + col]     = v2;
            C[(size_t)(row + 8) * HID + col + 1] = v3;
            rs[mi][0] += v0 + v1; rq[mi][0] += v0 * v0 + v1 * v1;
            rs[mi][1] += v2 + v3; rq[mi][1] += v2 * v2 + v3 * v3;
        }
    }
    if (sb >= 0) {
#pragma unroll
        for (int mi = 0; mi < 2; mi++)
#pragma unroll
            for (int rr = 0; rr < 2; rr++) {
                rs[mi][rr] += __shfl_xor_sync(0xffffffffu, rs[mi][rr], 1);
                rs[mi][rr] += __shfl_xor_sync(0xffffffffu, rs[mi][rr], 2);
                rq[mi][rr] += __shfl_xor_sync(0xffffffffu, rq[mi][rr], 1);
                rq[mi][rr] += __shfl_xor_sync(0xffffffffu, rq[mi][rr], 2);
            }
        if (qid == 0) {
#pragma unroll
            for (int mi = 0; mi < 2; mi++)
#pragma unroll
                for (int rr = 0; rr < 2; rr++) {
                    int row = rowbase + wm + mi * 16 + grp + rr * 8;
                    int n = row & 511;
                    atomicAdd(&g_bnsum[sb * NN + n], rs[mi][rr]);
                    atomicAdd(&g_bnsq [sb * NN + n], rq[mi][rr]);
                }
        }
    }
}

/* ------------- 6) BN finalize + apply + ReLU (fp16 stages) ------------- */
template<bool H16>
__global__ void k_bnapply(const float* __restrict__ g, const float* __restrict__ bb,
                          int sb) {
    int i4 = blockIdx.x * 256 + threadIdx.x;
    float4 v = ((const float4*)g_pre)[i4];
    int r = i4 >> 5;
    int n = r & 511;
    const float invC = 1.f / (float)(MBATCH * HID);
    float mean = g_bnsum[sb * NN + n] * invC;
    float var  = g_bnsq [sb * NN + n] * invC - mean * mean;
    var = fmaxf(var, 0.f);
    float sc = g[n] * rsqrtf(var + EPSV);
    float sh = bb[n] - mean * sc;
    float x0 = fmaxf(v.x * sc + sh, 0.f);
    float x1 = fmaxf(v.y * sc + sh, 0.f);
    float x2 = fmaxf(v.z * sc + sh, 0.f);
    float x3 = fmaxf(v.w * sc + sh, 0.f);
    __half2 p0 = __floats2half2_rn(x0, x1);
    __half2 p1 = __floats2half2_rn(x2, x3);
    uint2 u; u.x = *(unsigned*)&p0; u.y = *(unsigned*)&p1;
    ((uint2*)g_hh)[i4] = u;
    if (H16) {
        float w = g_inv[r];
        __half2 h0 = __floats2half2_rn(w * x0, w * x1);
        __half2 h1 = __floats2half2_rn(w * x2, w * x3);
        uint2 u2; u2.x = *(unsigned*)&h0; u2.y = *(unsigned*)&h1;
        ((uint2*)g_h16)[i4] = u2;
    }
}

/* ---------------- driver ------------------------------------------------ */
extern "C" void kernel_launch(void* const* d_in, const int* in_sizes, int n_in,
                              void* d_out, int out_size) {
    const float* x   = (const float*)d_in[0];
    const float* adj = (const float*)d_in[1];
    const float* ws[3] = {(const float*)d_in[2],  (const float*)d_in[8],  (const float*)d_in[14]};
    const float* bs[3] = {(const float*)d_in[3],  (const float*)d_in[9],  (const float*)d_in[15]};
    const float* we[3] = {(const float*)d_in[4],  (const float*)d_in[10], (const float*)d_in[16]};
    const float* be[3] = {(const float*)d_in[5],  (const float*)d_in[11], (const float*)d_in[17]};
    const float* bg[3] = {(const float*)d_in[6],  (const float*)d_in[12], (const float*)d_in[18]};
    const float* bb[3] = {(const float*)d_in[7],  (const float*)d_in[13], (const float*)d_in[19]};
    const float* w1  = (const float*)d_in[20];
    const float* b1  = (const float*)d_in[21];
    const float* bfg = (const float*)d_in[22];
    const float* bfb = (const float*)d_in[23];
    const float* w2  = (const float*)d_in[24];
    const float* b2  = (const float*)d_in[25];

    (void)in_sizes; (void)n_in; (void)out_size;

    k_csr<<<NB_CSR + NB_WPREP, 256>>>(adj,
        ws[0], we[0], be[0], ws[1], we[1], be[1], ws[2], we[2], be[2], w1, w2);
    k_deg<<<(MBATCH * NN) / 256, 256>>>();
    k_prep1<<<NB_SSUM + NB_STAGE0, 256>>>(x);

    /* layer 0 */
    k_agg<IN0><<<ROWS, 128>>>(x, KP0);
    k_gemm<<<ROWS / 128, 256>>>(KP0, bs[0], 0, nullptr, WT0, 0);
    k_bnapply<true><<<ROWS * HID / 4 / 256, 256>>>(bg[0], bb[0], 0);

    /* layer 1 */
    k_agg<HID><<<ROWS, 128>>>((const float*)nullptr, KP12);
    k_gemm<<<ROWS / 128, 256>>>(KP12, bs[1], 0, nullptr, WT1, 1);
    k_bnapply<true><<<ROWS * HID / 4 / 256, 256>>>(bg[1], bb[1], 1);

    /* layer 2 */
    k_agg<HID><<<ROWS, 128>>>((const float*)nullptr, KP12);
    k_gemm<<<ROWS / 128, 256>>>(KP12, bs[2], 0, nullptr, WT2, 2);
    k_bnapply<true><<<ROWS * HID / 4 / 256, 256>>>(bg[2], bb[2], 2);

    /* final MLP */
    k_gemm<<<ROWS / 128, 256>>>(HID, b1, 1, nullptr, WT3, 3);
    k_bnapply<false><<<ROWS * HID / 4 / 256, 256>>>(bfg, bfb, 3);
    k_gemm<<<ROWS / 128, 256>>>(HID, b2, 1, (float*)d_out, WT4, -1);
}

// round 17
// speedup vs baseline: 1.6981x; 1.0166x over previous
#include <cuda_runtime.h>
#include <cuda_fp16.h>

#define MBATCH 32
#define ET 4
#define NN 512
#define IN0 64
#define HID 128
#define ROWS (MBATCH*NN)      /* 16384 */
#define MAXNBR 64
#define KP0 352               /* pad(5*64+4, 32)  */
#define KP12 672              /* pad(5*128+4, 32) */
#define EPSV 1e-5f

/* transposed-weight column offsets inside g_Wt[128][WTCOLS] */
#define WT0 0
#define WT1 352
#define WT2 1024
#define WT3 1696
#define WT4 1824
#define WTCOLS 1952

#define NB_CSR    ((MBATCH*ET*NN)/8)              /* 8192 csr blocks */
#define NB_WPREP  ((HID*WTCOLS + 255)/256)        /* 976  */
#define NB_SSUM   ((MBATCH*ET*NN)/256)            /* 256  */
#define NB_STAGE0 ((MBATCH*NN*IN0/4)/256)         /* 1024 */

/* GEMM smem geometry */
#define SROW 40                                   /* halfs: 32 data + 8 pad */
#define STG_HALFS (128*SROW)                      /* halfs per stage per array */
#define GEMM_SMEM (3*STG_HALFS*2*2)               /* 3 stages, sA+sB, bytes = 61440 */

/* ---------------- static device scratch (no allocation) ---------------- */
__device__ float          g_inv[MBATCH*NN];
__device__ float          g_ssum[MBATCH*ET*NN];
__device__ __align__(16) unsigned short g_nbr[MBATCH*ET*NN*MAXNBR];  /* node idx */
__device__ int            g_cnt[MBATCH*ET*NN];              // clamped
__device__ int            g_cntfull[MBATCH*ET*NN];          // exact
__device__ __align__(16) __half g_A[ROWS*KP12];             // 22 MB
__device__ __align__(16) __half g_Wt[HID*WTCOLS];           // 0.5 MB
__device__ __align__(16) float  g_pre[ROWS*HID];            // 8.4 MB
__device__ __align__(16) __half g_hh[ROWS*HID];             // post-BN act, fp16
__device__ __align__(16) __half g_h16[ROWS*HID];            // inv-scaled act
__device__ __align__(16) __half g_x16[MBATCH*NN*IN0];       // inv-scaled x
__device__ float          g_bnsum[4*NN];
__device__ float          g_bnsq[4*NN];

/* ------------- 1) CSR build (+ fused weight prep in DRAM shadow) ------- */
__global__ void k_csr(const float* __restrict__ adj,
    const float* __restrict__ ws0, const float* __restrict__ we0, const float* __restrict__ be0,
    const float* __restrict__ ws1, const float* __restrict__ we1, const float* __restrict__ be1,
    const float* __restrict__ ws2, const float* __restrict__ we2, const float* __restrict__ be2,
    const float* __restrict__ w1,  const float* __restrict__ w2) {
    int blk = blockIdx.x;
    if (blk >= NB_CSR) {               /* ---- transposed weight prep ---- */
        int idx = (blk - NB_CSR) * 256 + threadIdx.x;
        if (idx >= HID * WTCOLS) return;
        int o = idx / WTCOLS, k = idx - o * WTCOLS;
        float v = 0.f;
        if (k < WT1) {
            int kk = k;
            if (kk < 64)       v = ws0[kk * HID + o];
            else if (kk < 320) { int e = (kk - 64) >> 6, j = (kk - 64) & 63;
                                 v = we0[j * (HID * ET) + o * ET + e]; }
            else if (kk < 324)   v = be0[o * ET + (kk - 320)];
        } else if (k < WT2) {
            int kk = k - WT1;
            if (kk < 128)      v = ws1[kk * HID + o];
            else if (kk < 640) { int e = (kk - 128) >> 7, j = (kk - 128) & 127;
                                 v = we1[j * (HID * ET) + o * ET + e]; }
            else if (kk < 644)   v = be1[o * ET + (kk - 640)];
        } else if (k < WT3) {
            int kk = k - WT2;
            if (kk < 128)      v = ws2[kk * HID + o];
            else if (kk < 640) { int e = (kk - 128) >> 7, j = (kk - 128) & 127;
                                 v = we2[j * (HID * ET) + o * ET + e]; }
            else if (kk < 644)   v = be2[o * ET + (kk - 640)];
        } else if (k < WT4) {
            v = w1[(k - WT3) * HID + o];
        } else {
            v = w2[(k - WT4) * HID + o];
        }
        g_Wt[o * WTCOLS + k] = __float2half_rn(v);
        return;
    }
    /* ---- CSR: one warp per (b,e,n) row ---- */
    int row  = blk * 8 + (threadIdx.x >> 5);
    int lane = threadIdx.x & 31;
    int n    = row & (NN - 1);
    const float4* p = (const float4*)(adj + (size_t)row * NN);
    unsigned short* out = g_nbr + (size_t)row * MAXNBR;
    int cnt = 0;
    for (int it = 0; it < NN / 128; it++) {
        float4 v = p[it * 32 + lane];
        int mb = (it * 32 + lane) * 4;
        float vc[4] = {v.x, v.y, v.z, v.w};
#pragma unroll
        for (int c = 0; c < 4; c++) {
            bool pr = (vc[c] != 0.f) && (mb + c != n);
            unsigned msk = __ballot_sync(0xffffffffu, pr);
            if (pr) {
                int pos = cnt + __popc(msk & ((1u << lane) - 1u));
                if (pos < MAXNBR) out[pos] = (unsigned short)(mb + c);
            }
            cnt += __popc(msk);
        }
    }
    if (lane == 0) {
        g_cnt[row]     = cnt < MAXNBR ? cnt : MAXNBR;
        g_cntfull[row] = cnt;
    }
}

/* ------------- 2) inv degree from exact counts (adj symmetric, 0/1) ---- */
__global__ void k_deg() {
    int i = blockIdx.x * 256 + threadIdx.x;
    int b = i >> 9, m = i & 511;
    int d = 0;
#pragma unroll
    for (int e = 0; e < ET; e++) d += g_cntfull[((b * ET + e) << 9) + m];
    g_inv[i] = d > 0 ? 1.f / (float)d : 0.f;
}

/* ------------- 3) fused prep: ssum | stage0 (block dispatch) ----------- */
__global__ void k_prep1(const float* __restrict__ x) {
    int blk = blockIdx.x;
    if (blk < NB_SSUM) {
        int lidx = blk * 256 + threadIdx.x;
        int b = lidx >> 11;
        int cnt = g_cnt[lidx];
        const unsigned short* nb = g_nbr + (size_t)lidx * MAXNBR;
        const float* invb = g_inv + b * NN;
        float s = 0.f;
        for (int i = 0; i < cnt; i++) s += invb[nb[i]];
        g_ssum[lidx] = s;
        if (lidx < 4 * NN) { g_bnsum[lidx] = 0.f; g_bnsq[lidx] = 0.f; }
        return;
    }
    blk -= NB_SSUM;
    {
        int i4 = blk * 256 + threadIdx.x;
        float4 v = ((const float4*)x)[i4];
        int r = i4 >> 4;
        float w = g_inv[r];
        __half2 h0 = __floats2half2_rn(w * v.x, w * v.y);
        __half2 h1 = __floats2half2_rn(w * v.z, w * v.w);
        uint2 u; u.x = *(unsigned*)&h0; u.y = *(unsigned*)&h1;
        ((uint2*)g_x16)[i4] = u;
    }
}

/* ------------- 4) sparse aggregation: u16 idx + fp16 tree-sum ---------- */
/* R13 form, frozen: single chain/warp, 32-reg cap, 100% theor. occupancy */
template<int IN>
__global__ void __launch_bounds__(128, 16) k_agg(const float* __restrict__ x0, int KP) {
    constexpr int VEC = IN / 32;   // 4 for IN=128, 2 for IN=64
    const __half* __restrict__ h16 = (IN == IN0) ? (const __half*)g_x16
                                                 : (const __half*)g_h16;
    int r = blockIdx.x, b = r >> 9, n = r & 511;
    int warp = threadIdx.x >> 5, lane = threadIdx.x & 31;
    __half* Arow = g_A + (size_t)r * KP;

    if (warp == 0) {   /* self-feature copy */
        if (IN == IN0) {
            float2 v = *(const float2*)(x0 + (size_t)r * IN + lane * 2);
            *(__half2*)(Arow + lane * 2) = __floats2half2_rn(v.x, v.y);
        } else {
            *(uint2*)(Arow + lane * 4) =
                *(const uint2*)((const __half*)g_hh + (size_t)r * IN + lane * 4);
        }
    }
    if (warp == 1) {   /* s-values + zero-pad tail */
        if (lane < ET)
            Arow[5 * IN + lane] = __float2half_rn(g_ssum[((b * ET + lane) << 9) + n]);
        for (int k = 5 * IN + 4 + lane; k < KP; k += 32) Arow[k] = __half(0.f);
    }

    int e = warp;
    int lidx = ((b * ET + e) << 9) + n;
    int cnt = g_cnt[lidx];
    const unsigned short* nb = g_nbr + (size_t)lidx * MAXNBR;
    const uint2* nbq = (const uint2*)nb;      /* 16 groups of 4 u16 */
    const __half* hb = h16 + (size_t)b * NN * IN + lane * VEC;

    float acc[VEC];
#pragma unroll
    for (int c = 0; c < VEC; c++) acc[c] = 0.f;

    int i = 0;
    if (cnt >= 4) {
        uint2 qc = nbq[0];                    /* index prefetch, distance 1 */
        for (; i + 4 <= cnt; i += 4) {
            int g = (i >> 2) + 1;
            uint2 qn = nbq[g < 16 ? g : 15];  /* clamp: no OOB on last row */
            int m0 = qc.x & 0xffff, m1 = qc.x >> 16;
            int m2 = qc.y & 0xffff, m3 = qc.y >> 16;
            if (VEC == 4) {
                uint2 f0 = *(const uint2*)(hb + (size_t)m0 * IN);
                uint2 f1 = *(const uint2*)(hb + (size_t)m1 * IN);
                uint2 f2 = *(const uint2*)(hb + (size_t)m2 * IN);
                uint2 f3 = *(const uint2*)(hb + (size_t)m3 * IN);
                /* fp16 depth-2 tree per half2 column, one convert per batch */
                __half2 sx = __hadd2(__hadd2(*(__half2*)&f0.x, *(__half2*)&f1.x),
                                     __hadd2(*(__half2*)&f2.x, *(__half2*)&f3.x));
                __half2 sy = __hadd2(__hadd2(*(__half2*)&f0.y, *(__half2*)&f1.y),
                                     __hadd2(*(__half2*)&f2.y, *(__half2*)&f3.y));
                float2 a = __half22float2(sx);
                float2 bb2 = __half22float2(sy);
                acc[0] += a.x; acc[1] += a.y; acc[2] += bb2.x; acc[3] += bb2.y;
            } else {
                unsigned f0 = *(const unsigned*)(hb + (size_t)m0 * IN);
                unsigned f1 = *(const unsigned*)(hb + (size_t)m1 * IN);
                unsigned f2 = *(const unsigned*)(hb + (size_t)m2 * IN);
                unsigned f3 = *(const unsigned*)(hb + (size_t)m3 * IN);
                __half2 s = __hadd2(__hadd2(*(__half2*)&f0, *(__half2*)&f1),
                                    __hadd2(*(__half2*)&f2, *(__half2*)&f3));
                float2 a = __half22float2(s);
                acc[0] += a.x; acc[1] += a.y;
            }
            qc = qn;
        }
    }
    for (; i < cnt; i++) {
        int m = nb[i];
        if (VEC == 4) {
            uint2 f0 = *(const uint2*)(hb + (size_t)m * IN);
            float2 a = __half22float2(*(__half2*)&f0.x);
            float2 bb2 = __half22float2(*(__half2*)&f0.y);
            acc[0] += a.x; acc[1] += a.y; acc[2] += bb2.x; acc[3] += bb2.y;
        } else {
            unsigned f0 = *(const unsigned*)(hb + (size_t)m * IN);
            float2 a = __half22float2(*(__half2*)&f0);
            acc[0] += a.x; acc[1] += a.y;
        }
    }

    if (VEC == 4) {
        __half2 o0 = __floats2half2_rn(acc[0], acc[1]);
        __half2 o1 = __floats2half2_rn(acc[2], acc[3]);
        uint2 u; u.x = *(unsigned*)&o0; u.y = *(unsigned*)&o1;
        *(uint2*)(Arow + IN + e * IN + lane * 4) = u;
    } else {
        *(__half2*)(Arow + IN + e * IN + lane * 2) = __floats2half2_rn(acc[0], acc[1]);
    }
}

/* ------------- 5) FP16 GEMM: 3-stage cp.async, ONE sync/iter ----------- */
__device__ __forceinline__ unsigned smaddr(const void* p) {
    return (unsigned)__cvta_generic_to_shared(p);
}
__device__ __forceinline__ void cpasync16(unsigned s, const void* g) {
    asm volatile("cp.async.cg.shared.global [%0], [%1], 16;\n" :: "r"(s), "l"(g));
}
__device__ __forceinline__ void ldsm4(unsigned& r0, unsigned& r1, unsigned& r2,
                                      unsigned& r3, unsigned addr) {
    asm volatile("ldmatrix.sync.aligned.m8n8.x4.shared.b16 {%0,%1,%2,%3}, [%4];\n"
                 : "=r"(r0), "=r"(r1), "=r"(r2), "=r"(r3) : "r"(addr));
}

__global__ void __launch_bounds__(256) k_gemm(int KP, const float* __restrict__ bias,
                                              int srcH, float* __restrict__ Cout,
                                              int wofs, int sb) {
    const __half* A = srcH ? (const __half*)g_hh : (const __half*)g_A;
    float* C = Cout ? Cout : (float*)g_pre;

    extern __shared__ __half dynsmem[];
    __half* sA = dynsmem;                         /* 3 stages × STG_HALFS */
    __half* sB = dynsmem + 3 * STG_HALFS;
    const unsigned STGB = STG_HALFS * 2;          /* bytes per stage */

    int tid = threadIdx.x;
    int lane = tid & 31, warp = tid >> 5;
    int wm = (warp >> 1) * 32, wn = (warp & 1) * 64;
    int grp = lane >> 2, qid = lane & 3;
    int rowbase = blockIdx.x * 128;
    int KB = KP >> 5;

    unsigned aBase = smaddr(sA);
    unsigned bBase = smaddr(sB);
    int l7 = lane & 7, lb3 = (lane >> 3) & 1, lb4 = lane >> 4;
    unsigned aOff[2], bOff[4];
#pragma unroll
    for (int mi = 0; mi < 2; mi++)
        aOff[mi] = ((wm + mi * 16 + lb3 * 8 + l7) * SROW + lb4 * 8) * 2;
#pragma unroll
    for (int p = 0; p < 4; p++)
        bOff[p] = ((wn + p * 16 + lb4 * 8 + l7) * SROW + lb3 * 8) * 2;

    float acc[2][8][4];
#pragma unroll
    for (int a = 0; a < 2; a++)
#pragma unroll
        for (int bq = 0; bq < 8; bq++)
#pragma unroll
            for (int c = 0; c < 4; c++) acc[a][bq][c] = 0.f;

    auto issue = [&](int kb, int buf) {
        int kof = kb * 32;
        __half* dA = sA + buf * STG_HALFS;
        __half* dB = sB + buf * STG_HALFS;
#pragma unroll
        for (int i = 0; i < 2; i++) {
            int c = tid + i * 256, row = c >> 2, q = c & 3;
            cpasync16(smaddr(dA + row * SROW + q * 8),
                      A + (size_t)(rowbase + row) * KP + kof + q * 8);
            cpasync16(smaddr(dB + row * SROW + q * 8),
                      (const __half*)g_Wt + (size_t)row * WTCOLS + wofs + kof + q * 8);
        }
        asm volatile("cp.async.commit_group;\n" ::);
    };

    issue(0, 0);
    if (KB > 1) issue(1, 1);
    for (int kb = 0; kb < KB; kb++) {
        int buf = kb % 3;
        if (kb + 1 < KB) {
            asm volatile("cp.async.wait_group 1;\n" ::);
        } else {
            asm volatile("cp.async.wait_group 0;\n" ::);
        }
        __syncthreads();                          /* single barrier per iter */
        if (kb + 2 < KB) issue(kb + 2, (kb + 2) % 3);

#pragma unroll
        for (int ks = 0; ks < 2; ks++) {
            unsigned kby = ks * 32 + buf * STGB;
            unsigned bf[8][2];
#pragma unroll
            for (int p = 0; p < 4; p++)
                ldsm4(bf[2*p][0], bf[2*p][1], bf[2*p+1][0], bf[2*p+1][1],
                      bBase + bOff[p] + kby);
#pragma unroll
            for (int mi = 0; mi < 2; mi++) {
                unsigned a0, a1, a2, a3;
                ldsm4(a0, a1, a2, a3, aBase + aOff[mi] + kby);
#pragma unroll
                for (int ni = 0; ni < 8; ni++) {
                    asm volatile(
                        "mma.sync.aligned.m16n8k16.row.col.f32.f16.f16.f32 "
                        "{%0,%1,%2,%3}, {%4,%5,%6,%7}, {%8,%9}, {%0,%1,%2,%3};\n"
                        : "+f"(acc[mi][ni][0]), "+f"(acc[mi][ni][1]),
                          "+f"(acc[mi][ni][2]), "+f"(acc[mi][ni][3])
                        : "r"(a0), "r"(a1), "r"(a2), "r"(a3),
                          "r"(bf[ni][0]), "r"(bf[ni][1]));
                }
            }
        }
    }

    /* epilogue: +bias, store, per-row BN partial sums */
    float rs[2][2] = {{0.f,0.f},{0.f,0.f}};
    float rq[2][2] = {{0.f,0.f},{0.f,0.f}};
#pragma unroll
    for (int mi = 0; mi < 2; mi++) {
        int row = rowbase + wm + mi * 16 + grp;
#pragma unroll
        for (int ni = 0; ni < 8; ni++) {
            int col = wn + ni * 8 + qid * 2;
            float b0 = bias[col], b1 = bias[col + 1];
            float v0 = acc[mi][ni][0] + b0, v1 = acc[mi][ni][1] + b1;
            float v2 = acc[mi][ni][2] + b0, v3 = acc[mi][ni][3] + b1;
            C[(size_t)row * HID + col]           = v0;
            C[(size_t)row * HID + col + 1]       = v1;
            C[(size_t)(row + 8) * HID + col]     = v2;
            C[(size_t)(row + 8) * HID + col + 1] = v3;
            rs[mi][0] += v0 + v1; rq[mi][0] += v0 * v0 + v1 * v1;
            rs[mi][1] += v2 + v3; rq[mi][1] += v2 * v2 + v3 * v3;
        }
    }
    if (sb >= 0) {
#pragma unroll
        for (int mi = 0; mi < 2; mi++)
#pragma unroll
            for (int rr = 0; rr < 2; rr++) {
                rs[mi][rr] += __shfl_xor_sync(0xffffffffu, rs[mi][rr], 1);
                rs[mi][rr] += __shfl_xor_sync(0xffffffffu, rs[mi][rr], 2);
                rq[mi][rr] += __shfl_xor_sync(0xffffffffu, rq[mi][rr], 1);
                rq[mi][rr] += __shfl_xor_sync(0xffffffffu, rq[mi][rr], 2);
            }
        if (qid == 0) {
#pragma unroll
            for (int mi = 0; mi < 2; mi++)
#pragma unroll
                for (int rr = 0; rr < 2; rr++) {
                    int row = rowbase + wm + mi * 16 + grp + rr * 8;
                    int n = row & 511;
                    atomicAdd(&g_bnsum[sb * NN + n], rs[mi][rr]);
                    atomicAdd(&g_bnsq [sb * NN + n], rq[mi][rr]);
                }
        }
    }
}

/* ------------- 6) BN finalize + apply + ReLU (fp16 stages) ------------- */
template<bool H16>
__global__ void k_bnapply(const float* __restrict__ g, const float* __restrict__ bb,
                          int sb) {
    int i4 = blockIdx.x * 256 + threadIdx.x;
    float4 v = ((const float4*)g_pre)[i4];
    int r = i4 >> 5;
    int n = r & 511;
    const float invC = 1.f / (float)(MBATCH * HID);
    float mean = g_bnsum[sb * NN + n] * invC;
    float var  = g_bnsq [sb * NN + n] * invC - mean * mean;
    var = fmaxf(var, 0.f);
    float sc = g[n] * rsqrtf(var + EPSV);
    float sh = bb[n] - mean * sc;
    float x0 = fmaxf(v.x * sc + sh, 0.f);
    float x1 = fmaxf(v.y * sc + sh, 0.f);
    float x2 = fmaxf(v.z * sc + sh, 0.f);
    float x3 = fmaxf(v.w * sc + sh, 0.f);
    __half2 p0 = __floats2half2_rn(x0, x1);
    __half2 p1 = __floats2half2_rn(x2, x3);
    uint2 u; u.x = *(unsigned*)&p0; u.y = *(unsigned*)&p1;
    ((uint2*)g_hh)[i4] = u;
    if (H16) {
        float w = g_inv[r];
        __half2 h0 = __floats2half2_rn(w * x0, w * x1);
        __half2 h1 = __floats2half2_rn(w * x2, w * x3);
        uint2 u2; u2.x = *(unsigned*)&h0; u2.y = *(unsigned*)&h1;
        ((uint2*)g_h16)[i4] = u2;
    }
}

/* ---------------- driver ------------------------------------------------ */
extern "C" void kernel_launch(void* const* d_in, const int* in_sizes, int n_in,
                              void* d_out, int out_size) {
    const float* x   = (const float*)d_in[0];
    const float* adj = (const float*)d_in[1];
    const float* ws[3] = {(const float*)d_in[2],  (const float*)d_in[8],  (const float*)d_in[14]};
    const float* bs[3] = {(const float*)d_in[3],  (const float*)d_in[9],  (const float*)d_in[15]};
    const float* we[3] = {(const float*)d_in[4],  (const float*)d_in[10], (const float*)d_in[16]};
    const float* be[3] = {(const float*)d_in[5],  (const float*)d_in[11], (const float*)d_in[17]};
    const float* bg[3] = {(const float*)d_in[6],  (const float*)d_in[12], (const float*)d_in[18]};
    const float* bb[3] = {(const float*)d_in[7],  (const float*)d_in[13], (const float*)d_in[19]};
    const float* w1  = (const float*)d_in[20];
    const float* b1  = (const float*)d_in[21];
    const float* bfg = (const float*)d_in[22];
    const float* bfb = (const float*)d_in[23];
    const float* w2  = (const float*)d_in[24];
    const float* b2  = (const float*)d_in[25];

    (void)in_sizes; (void)n_in; (void)out_size;

    static int smem_set = 0;
    if (!smem_set) {
        cudaFuncSetAttribute(k_gemm, cudaFuncAttributeMaxDynamicSharedMemorySize,
                             GEMM_SMEM);
        smem_set = 1;
    }

    k_csr<<<NB_CSR + NB_WPREP, 256>>>(adj,
        ws[0], we[0], be[0], ws[1], we[1], be[1], ws[2], we[2], be[2], w1, w2);
    k_deg<<<(MBATCH * NN) / 256, 256>>>();
    k_prep1<<<NB_SSUM + NB_STAGE0, 256>>>(x);

    /* layer 0 */
    k_agg<IN0><<<ROWS, 128>>>(x, KP0);
    k_gemm<<<ROWS / 128, 256, GEMM_SMEM>>>(KP0, bs[0], 0, nullptr, WT0, 0);
    k_bnapply<true><<<ROWS * HID / 4 / 256, 256>>>(bg[0], bb[0], 0);

    /* layer 1 */
    k_agg<HID><<<ROWS, 128>>>((const float*)nullptr, KP12);
    k_gemm<<<ROWS / 128, 256, GEMM_SMEM>>>(KP12, bs[1], 0, nullptr, WT1, 1);
    k_bnapply<true><<<ROWS * HID / 4 / 256, 256>>>(bg[1], bb[1], 1);

    /* layer 2 */
    k_agg<HID><<<ROWS, 128>>>((const float*)nullptr, KP12);
    k_gemm<<<ROWS / 128, 256, GEMM_SMEM>>>(KP12, bs[2], 0, nullptr, WT2, 2);
    k_bnapply<true><<<ROWS * HID / 4 / 256, 256>>>(bg[2], bb[2], 2);

    /* final MLP */
    k_gemm<<<ROWS / 128, 256, GEMM_SMEM>>>(HID, b1, 1, nullptr, WT3, 3);
    k_bnapply<false><<<ROWS * HID / 4 / 256, 256>>>(bfg, bfb, 3);
    k_gemm<<<ROWS / 128, 256, GEMM_SMEM>>>(HID, b2, 1, (float*)d_out, WT4, -1);
}